// round 1
// baseline (speedup 1.0000x reference)
#include <cuda_runtime.h>
#include <math.h>

#define SEQ    2048
#define DMODEL 2048
#define NHEADS 16

#define NEGINF (-1e30f)

// ---------------- scratch ----------------
__device__ float g_q[SEQ * 128];    // tanh(q proj)  [S][H*8]
__device__ float g_k[SEQ * 32];     // tanh(k proj)  [S][KV*8]
__device__ float g_v[SEQ * 32];     // sigmoid(v)    [S][KV*8]
__device__ float g_attn[SEQ * 128]; // attention out [S][H*8]

// ---------------- Pass A: fused QKV projection ----------------
// P = X @ [Wq;Wk;Wv]^T  (M=2048, N=192, K=2048), epilogue activations.
__global__ __launch_bounds__(256) void proj_kernel(
    const float* __restrict__ X,
    const float* __restrict__ Wq,
    const float* __restrict__ Wk,
    const float* __restrict__ Wv,
    const float* __restrict__ tau)
{
    __shared__ float As[16][68];
    __shared__ float Bs[16][68];
    const int m0 = blockIdx.x * 64;
    const int n0 = blockIdx.y * 64;
    const int t  = threadIdx.x;
    const int lm  = t >> 2;          // 0..63 (tile row for loads)
    const int lk4 = (t & 3) << 2;    // 0,4,8,12
    const int mm  = (t >> 4) << 2;   // compute tile coords
    const int nn  = (t & 15) << 2;
    const float inv_tau = 1.0f / tau[0];

    const int n = n0 + lm;
    const float* wrow;
    if (n < 128)      wrow = Wq + n * DMODEL;
    else if (n < 160) wrow = Wk + (n - 128) * DMODEL;
    else              wrow = Wv + (n - 160) * DMODEL;
    const float* xrow = X + (m0 + lm) * DMODEL;

    float acc[4][4] = {};
    for (int k0 = 0; k0 < DMODEL; k0 += 16) {
        float4 av = *(const float4*)(xrow + k0 + lk4);
        float4 bv = *(const float4*)(wrow + k0 + lk4);
        As[lk4 + 0][lm] = av.x; As[lk4 + 1][lm] = av.y;
        As[lk4 + 2][lm] = av.z; As[lk4 + 3][lm] = av.w;
        Bs[lk4 + 0][lm] = bv.x; Bs[lk4 + 1][lm] = bv.y;
        Bs[lk4 + 2][lm] = bv.z; Bs[lk4 + 3][lm] = bv.w;
        __syncthreads();
        #pragma unroll
        for (int kk = 0; kk < 16; ++kk) {
            float4 a4 = *(const float4*)&As[kk][mm];
            float4 b4 = *(const float4*)&Bs[kk][nn];
            float ar[4] = {a4.x, a4.y, a4.z, a4.w};
            float br[4] = {b4.x, b4.y, b4.z, b4.w};
            #pragma unroll
            for (int i = 0; i < 4; ++i)
                #pragma unroll
                for (int j = 0; j < 4; ++j)
                    acc[i][j] = fmaf(ar[i], br[j], acc[i][j]);
        }
        __syncthreads();
    }
    #pragma unroll
    for (int i = 0; i < 4; ++i) {
        const int m = m0 + mm + i;
        #pragma unroll
        for (int j = 0; j < 4; ++j) {
            const int nc = n0 + nn + j;
            const float x = acc[i][j] * inv_tau;
            if (nc < 128)      g_q[m * 128 + nc]        = tanhf(x);
            else if (nc < 160) g_k[m * 32 + (nc - 128)] = tanhf(x);
            else               g_v[m * 32 + (nc - 160)] = 1.0f / (1.0f + expf(-x));
        }
    }
}

// ---------------- Pass B: fused suffix attention ----------------
// CTA = (head h, query block of 64). Score via diagonal-band prefix trick:
//   score(q,k) = (D[a+31][b+31] - D[a-1][b-1]) * scale + k/(q+1)/tau,  k < q
// with G[i,j] = dot8(q8[i], k8[j]) over the 96x96 halo tile,
// D = diagonal running prefix of G.
__global__ __launch_bounds__(256) void attn_kernel(const float* __restrict__ tau)
{
    __shared__ float qs[96][8];       // q halo rows
    __shared__ float ks[96 * 9];      // k halo rows (stride 9: conflict-free G loads)
    __shared__ float vsm[64][8];      // shifted v rows for this key tile
    __shared__ float G[96 * 100];     // stride 100: conflict-free D reads (4a+jq)

    const int h  = blockIdx.y;
    const int qb = 31 - blockIdx.x;   // big blocks scheduled first
    const int q0 = qb * 64;
    const int c  = h >> 2;            // GQA kv head
    const int t  = threadIdx.x;
    const float inv_tau = 1.0f / tau[0];
    const float scale   = 0.0625f * inv_tau;   // 1/sqrt(256)/tau

    // load q halo once: rows q0-31 .. q0+64
    if (t < 192) {
        const int r = t >> 1, half = t & 1;
        const int gq = q0 - 31 + r;
        float4 v4 = make_float4(0.f, 0.f, 0.f, 0.f);
        if (gq >= 0 && gq < SEQ) v4 = *(const float4*)&g_q[gq * 128 + h * 8 + half * 4];
        *(float4*)&qs[r][half * 4] = v4;
    }

    const int a  = t >> 2;            // query row within block (0..63)
    const int jq = t & 3;             // 4 threads share a row (strided k)
    const int qg = q0 + a;
    const float bias_r = inv_tau / (float)(qg + 1);

    float m_run = NEGINF, l_run = 0.0f;
    float acc[8];
    #pragma unroll
    for (int d = 0; d < 8; ++d) acc[d] = 0.0f;

    const int ty = t >> 4, tx = t & 15;   // 16x16 grid, 6x6 G entries each
    const int i0 = ty * 6, j0 = tx * 6;

    for (int kb = 0; kb <= qb; ++kb) {
        const int k0 = kb * 64;
        __syncthreads();   // previous score stage done with vsm/G

        // load k halo + shifted v
        if (t < 192) {
            const int r = t >> 1, half = t & 1;
            const int gk = k0 - 31 + r;
            float4 v4 = make_float4(0.f, 0.f, 0.f, 0.f);
            if (gk >= 0 && gk < SEQ) v4 = *(const float4*)&g_k[gk * 32 + c * 8 + half * 4];
            float* p = &ks[r * 9 + half * 4];
            p[0] = v4.x; p[1] = v4.y; p[2] = v4.z; p[3] = v4.w;
        } else {
            const int u = t - 192;
            #pragma unroll
            for (int rep = 0; rep < 2; ++rep) {
                const int idx = u * 2 + rep;
                const int r = idx >> 1, half = idx & 1;
                const int gk = k0 + r + 1;  // vs[k] = v[k+1]
                float4 v4 = make_float4(0.f, 0.f, 0.f, 0.f);
                if (gk < SEQ) v4 = *(const float4*)&g_v[gk * 32 + c * 8 + half * 4];
                *(float4*)&vsm[r][half * 4] = v4;
            }
        }
        __syncthreads();

        // G compute: each thread a 6x6 block of 8-dim dots
        float gacc[6][6] = {};
        #pragma unroll
        for (int d = 0; d < 8; ++d) {
            float qd[6], kd[6];
            #pragma unroll
            for (int ii = 0; ii < 6; ++ii) qd[ii] = qs[i0 + ii][d];
            #pragma unroll
            for (int jj = 0; jj < 6; ++jj) kd[jj] = ks[(j0 + jj) * 9 + d];
            #pragma unroll
            for (int ii = 0; ii < 6; ++ii)
                #pragma unroll
                for (int jj = 0; jj < 6; ++jj)
                    gacc[ii][jj] = fmaf(qd[ii], kd[jj], gacc[ii][jj]);
        }
        #pragma unroll
        for (int ii = 0; ii < 6; ++ii)
            #pragma unroll
            for (int jj = 0; jj < 6; ++jj)
                G[(i0 + ii) * 100 + (j0 + jj)] = gacc[ii][jj];
        __syncthreads();

        // diagonal prefix: D[i][j] = G[i][j] + D[i-1][j-1]
        if (t < 191) {
            const int dlt = t - 95;
            const int ad = dlt < 0 ? -dlt : dlt;
            const int ip = dlt > 0 ? dlt : 0;
            const int jp = dlt > 0 ? 0 : -dlt;
            const int L  = 96 - ad;
            float carry = 0.0f;
            int off = ip * 100 + jp;
            for (int s2 = 0; s2 < L; ++s2) {
                carry += G[off];
                G[off] = carry;
                off += 101;
            }
        }
        __syncthreads();

        // scores + online softmax (each thread: k = k0 + jq, jq+4, ..., jq+60)
        float sv[16];
        float tmax = NEGINF;
        const int browH = (a + 31) * 100 + 31;
        const int browL = (a - 1) * 100 - 1;
        #pragma unroll
        for (int bb = 0; bb < 16; ++bb) {
            const int b  = (bb << 2) | jq;
            const int kg = k0 + b;
            float s = NEGINF;
            if (kg < qg) {
                const float hi = G[browH + b];
                const float lo = (a > 0 && b > 0) ? G[browL + b] : 0.0f;
                s = (hi - lo) * scale + (float)kg * bias_r;
            }
            sv[bb] = s;
            tmax = fmaxf(tmax, s);
        }
        if (tmax > NEGINF) {
            const float nm = fmaxf(m_run, tmax);
            if (m_run > NEGINF && nm > m_run) {
                const float f = __expf(m_run - nm);
                l_run *= f;
                #pragma unroll
                for (int d = 0; d < 8; ++d) acc[d] *= f;
            }
            m_run = nm;
            #pragma unroll
            for (int bb = 0; bb < 16; ++bb) {
                if (sv[bb] > NEGINF) {
                    const float e = __expf(sv[bb] - m_run);
                    l_run += e;
                    const int b = (bb << 2) | jq;
                    #pragma unroll
                    for (int d = 0; d < 8; ++d)
                        acc[d] = fmaf(e, vsm[b][d], acc[d]);
                }
            }
        }
    }

    // merge the 4 threads of each query row (online-softmax combine via shfl)
    #pragma unroll
    for (int off = 1; off < 4; off <<= 1) {
        const float mo  = __shfl_xor_sync(0xffffffffu, m_run, off);
        const float lo2 = __shfl_xor_sync(0xffffffffu, l_run, off);
        const float nm = fmaxf(m_run, mo);
        const float f1 = (m_run > NEGINF) ? __expf(m_run - nm) : 0.0f;
        const float f2 = (mo    > NEGINF) ? __expf(mo    - nm) : 0.0f;
        l_run = l_run * f1 + lo2 * f2;
        #pragma unroll
        for (int d = 0; d < 8; ++d) {
            const float ao = __shfl_xor_sync(0xffffffffu, acc[d], off);
            acc[d] = acc[d] * f1 + ao * f2;
        }
        m_run = nm;
    }
    if (jq == 0) {
        const float invl = (l_run > 0.0f) ? 1.0f / l_run : 0.0f;
        #pragma unroll
        for (int d = 0; d < 8; ++d)
            g_attn[qg * 128 + h * 8 + d] = acc[d] * invl;
    }
}

// ---------------- Pass C: affine + output projection ----------------
// out[m][n] = sum_j (attn[m][j]*(ve1-ve0)+ve0) * Wo[n][j]   (M=N=2048, K=128)
__global__ __launch_bounds__(256) void out_kernel(
    const float* __restrict__ Wo,
    const float* __restrict__ ve0,
    const float* __restrict__ ve1,
    float* __restrict__ out)
{
    __shared__ float As[16][68];
    __shared__ float Bs[16][68];
    const int m0 = blockIdx.x * 64;
    const int n0 = blockIdx.y * 64;
    const int t  = threadIdx.x;
    const int lm  = t >> 2;
    const int lk4 = (t & 3) << 2;
    const int mm  = (t >> 4) << 2;
    const int nn  = (t & 15) << 2;

    const float* arow = g_attn + (m0 + lm) * 128;
    const float* brow = Wo + (n0 + lm) * 128;

    float acc[4][4] = {};
    for (int k0 = 0; k0 < 128; k0 += 16) {
        float4 av = *(const float4*)(arow + k0 + lk4);
        const float4 e0 = *(const float4*)(ve0 + k0 + lk4);
        const float4 e1 = *(const float4*)(ve1 + k0 + lk4);
        av.x = av.x * (e1.x - e0.x) + e0.x;
        av.y = av.y * (e1.y - e0.y) + e0.y;
        av.z = av.z * (e1.z - e0.z) + e0.z;
        av.w = av.w * (e1.w - e0.w) + e0.w;
        const float4 bv = *(const float4*)(brow + k0 + lk4);
        As[lk4 + 0][lm] = av.x; As[lk4 + 1][lm] = av.y;
        As[lk4 + 2][lm] = av.z; As[lk4 + 3][lm] = av.w;
        Bs[lk4 + 0][lm] = bv.x; Bs[lk4 + 1][lm] = bv.y;
        Bs[lk4 + 2][lm] = bv.z; Bs[lk4 + 3][lm] = bv.w;
        __syncthreads();
        #pragma unroll
        for (int kk = 0; kk < 16; ++kk) {
            float4 a4 = *(const float4*)&As[kk][mm];
            float4 b4 = *(const float4*)&Bs[kk][nn];
            float ar[4] = {a4.x, a4.y, a4.z, a4.w};
            float br[4] = {b4.x, b4.y, b4.z, b4.w};
            #pragma unroll
            for (int i = 0; i < 4; ++i)
                #pragma unroll
                for (int j = 0; j < 4; ++j)
                    acc[i][j] = fmaf(ar[i], br[j], acc[i][j]);
        }
        __syncthreads();
    }
    #pragma unroll
    for (int i = 0; i < 4; ++i)
        #pragma unroll
        for (int j = 0; j < 4; ++j)
            out[(m0 + mm + i) * DMODEL + (n0 + nn + j)] = acc[i][j];
}

// ---------------- launch ----------------
extern "C" void kernel_launch(void* const* d_in, const int* in_sizes, int n_in,
                              void* d_out, int out_size)
{
    const float* X   = (const float*)d_in[0];
    const float* Wq  = (const float*)d_in[1];
    const float* Wk  = (const float*)d_in[2];
    const float* Wv  = (const float*)d_in[3];
    const float* Wo  = (const float*)d_in[4];
    const float* ve0 = (const float*)d_in[5];
    const float* ve1 = (const float*)d_in[6];
    const float* tau = (const float*)d_in[7];
    float* out = (float*)d_out;
    (void)in_sizes; (void)n_in; (void)out_size;

    proj_kernel<<<dim3(32, 3),  256>>>(X, Wq, Wk, Wv, tau);
    attn_kernel<<<dim3(32, 16), 256>>>(tau);
    out_kernel <<<dim3(32, 32), 256>>>(Wo, ve0, ve1, out);
}